// round 17
// baseline (speedup 1.0000x reference)
#include <cuda_runtime.h>
#include <math.h>

#define S_   8192
#define B_   2
#define D_   512
#define H_   2048
#define QK_  128
#define NCAT (H_ + QK_)   // 2176
#define GSZ_ 256
#define KS_  17
#define BS_  (B_*S_)
#define NGRP 32
#define NSPLIT 8

// ---------------- scratch ----------------
__device__ float g_hstate[BS_*D_];
__device__ float g_yln[BS_*D_];
__device__ float g_hq[(size_t)BS_*NCAT];
__device__ float g_h1[(size_t)BS_*H_];
__device__ float g_h2[(size_t)BS_*H_];
__device__ float g_qk2[BS_*QK_];
__device__ float g_blk[BS_*QK_];
__device__ float g_o1[BS_*D_];
__device__ float g_lkvup[(size_t)B_*NSPLIT*QK_*H_];
__device__ float g_bcat[NCAT];
__device__ float g_ps[BS_];
__device__ float g_ps2[BS_];
__device__ float g_stats[4];
// pre-split uint2 {hi,lo} bf16x2 buffers
__device__ uint2 g_psnx[(size_t)BS_*(D_/2)];
__device__ uint2 g_pswcat[(D_/2)*NCAT];
__device__ uint2 g_psbqq[(size_t)BS_*(QK_/2)];
__device__ uint2 g_psblq[(size_t)BS_*(QK_/2)];
__device__ uint2 g_psbkq[(size_t)BS_*(QK_/2)];
__device__ uint2 g_psattn[(size_t)B_*NGRP*GSZ_*(GSZ_/2)];
__device__ uint2 g_psh2[(size_t)(BS_/2)*H_];
__device__ uint2 g_psgate[(size_t)BS_*D_];          // K=1024 -> 512 kpairs
__device__ uint2 g_pswo[(D_)*(D_)];                 // 512 kpairs x 512
__device__ uint2 g_pslkvu[B_*(QK_/2)*H_];

// ---------------- helpers ----------------
__device__ __forceinline__ float blockReduceSum(float v, float* red, int n) {
    int tid = threadIdx.x;
    red[tid] = v; __syncthreads();
    for (int o = n >> 1; o > 0; o >>= 1) {
        if (tid < o) red[tid] += red[tid + o];
        __syncthreads();
    }
    float r = red[0];
    __syncthreads();
    return r;
}

__device__ __forceinline__ uint2 packpair2(float v0, float v1) {
    unsigned h, l;
    asm("cvt.rn.bf16x2.f32 %0, %1, %2;" : "=r"(h) : "f"(v1), "f"(v0));
    float h0 = __uint_as_float(h << 16);
    float h1 = __uint_as_float(h & 0xFFFF0000u);
    float r0 = v0 - h0;
    float r1 = v1 - h1;
    asm("cvt.rn.bf16x2.f32 %0, %1, %2;" : "=r"(l) : "f"(r1), "f"(r0));
    return make_uint2(h, l);
}

#define MMA_BF16(Cx, A4, B2)                                               \
    asm volatile(                                                          \
        "mma.sync.aligned.m16n8k16.row.col.f32.bf16.bf16.f32 "             \
        "{%0,%1,%2,%3},{%4,%5,%6,%7},{%8,%9},{%0,%1,%2,%3};"               \
        : "+f"(Cx[0]), "+f"(Cx[1]), "+f"(Cx[2]), "+f"(Cx[3])               \
        : "r"(A4[0]), "r"(A4[1]), "r"(A4[2]), "r"(A4[3]),                  \
          "r"(B2[0]), "r"(B2[1]))

// ---------------- 3xBF16 split GEMM, pre-split operands ----------------
// AM: 1=fp32 TA [K][lda] (packpair in loader), 2=presplit row-major [M][lda(u2)]
// BM: 2=presplit K-major [kp][ldb], 3=presplit TB row-major [N][ldb(u2)]
// OPS: 0=fp32 C, 1=presplit uint2 C (row-major kpairs)
#define TBM 128
#define TBN 128
#define TBK 16
#define KP  (TBK/2)
#define SPAD 8
template<int EPI, int AM, int BM, bool ACC, int OPS>
__global__ void __launch_bounds__(256, 2) tgemm_k(
    const void* __restrict__ Av, const void* __restrict__ Bv,
    void* __restrict__ Cv, const float* __restrict__ bias,
    float alpha_c, int M, int N, int K, int lda, int ldb, int ldc,
    long long sA, long long sB, long long sC, int split)
{
    __shared__ unsigned Ash[2][KP][TBM + SPAD];
    __shared__ unsigned Asl[2][KP][TBM + SPAD];
    __shared__ unsigned Bsh[2][KP][TBN + SPAD];
    __shared__ unsigned Bsl[2][KP][TBN + SPAD];

    const int z = blockIdx.z;
    const int bb = z / split;
    const int sp = z - bb * split;

    const float* Af = nullptr; const uint2* Aps = nullptr;
    if (AM == 1) Af  = ((const float*)Av) + bb * sA + (long long)sp * K * lda;
    if (AM == 2) Aps = ((const uint2*)Av) + bb * sA + (long long)sp * (K / 2);
    const uint2* Bps = nullptr;
    if (BM == 2) Bps = ((const uint2*)Bv) + bb * sB + (long long)sp * (K / 2) * ldb;
    if (BM == 3) Bps = ((const uint2*)Bv) + bb * sB + (long long)sp * (K / 2);
    float* Cf = nullptr; uint2* Cps = nullptr;
    if (OPS == 0) Cf  = ((float*)Cv) + (long long)z * sC;
    else          Cps = ((uint2*)Cv) + (long long)z * sC;

    const int m0 = blockIdx.y * TBM, n0 = blockIdx.x * TBN;
    const int tid = threadIdx.x;
    const int w = tid >> 5, lane = tid & 31;
    const int wm = (w >> 2) * 64, wn = (w & 3) * 32;
    const int r = lane >> 2, c = lane & 3;

    float acc[4][4][4];
    #pragma unroll
    for (int i = 0; i < 4; i++)
        #pragma unroll
        for (int j = 0; j < 4; j++)
            #pragma unroll
            for (int e = 0; e < 4; e++) acc[i][j][e] = 0.f;

    const int nk = K / TBK;
    float4 pa[2];
    uint2 pa2[4], pb2[4];

    auto loadA = [&](int kt) {
        if (AM == 2) {
            #pragma unroll
            for (int i = 0; i < 4; i++) {
                int idx = tid + i * 256;
                int m = idx >> 3, kp = idx & 7;
                pa2[i] = Aps[(long long)(m0 + m) * lda + kt * 8 + kp];
            }
        } else {
            #pragma unroll
            for (int i = 0; i < 2; i++) {
                int idx = tid + i * 256;
                int kp = idx >> 6, mp = idx & 63;
                float2 a0 = *(const float2*)&Af[(long long)(kt * TBK + 2*kp    ) * lda + m0 + 2*mp];
                float2 a1 = *(const float2*)&Af[(long long)(kt * TBK + 2*kp + 1) * lda + m0 + 2*mp];
                pa[i] = make_float4(a0.x, a1.x, a0.y, a1.y);
            }
        }
    };
    auto loadB = [&](int kt) {
        #pragma unroll
        for (int i = 0; i < 4; i++) {
            int idx = tid + i * 256;
            if (BM == 2) {
                int kp = idx >> 7, n = idx & 127;
                pb2[i] = Bps[(long long)(kt * 8 + kp) * ldb + n0 + n];
            } else {
                int n = idx >> 3, kp = idx & 7;
                pb2[i] = Bps[(long long)(n0 + n) * ldb + kt * 8 + kp];
            }
        }
    };
    auto stsAB = [&](int buf) {
        if (AM == 2) {
            #pragma unroll
            for (int i = 0; i < 4; i++) {
                int idx = tid + i * 256;
                int m = idx >> 3, kp = idx & 7;
                Ash[buf][kp][m] = pa2[i].x;
                Asl[buf][kp][m] = pa2[i].y;
            }
        } else {
            #pragma unroll
            for (int i = 0; i < 2; i++) {
                int idx = tid + i * 256;
                int kp = idx >> 6, mp = idx & 63;
                uint2 q0 = packpair2(pa[i].x, pa[i].y);
                uint2 q1 = packpair2(pa[i].z, pa[i].w);
                Ash[buf][kp][2*mp] = q0.x;  Ash[buf][kp][2*mp + 1] = q1.x;
                Asl[buf][kp][2*mp] = q0.y;  Asl[buf][kp][2*mp + 1] = q1.y;
            }
        }
        #pragma unroll
        for (int i = 0; i < 4; i++) {
            int idx = tid + i * 256;
            if (BM == 2) {
                int kp = idx >> 7, n = idx & 127;
                Bsh[buf][kp][n] = pb2[i].x;
                Bsl[buf][kp][n] = pb2[i].y;
            } else {
                int n = idx >> 3, kp = idx & 7;
                Bsh[buf][kp][n] = pb2[i].x;
                Bsl[buf][kp][n] = pb2[i].y;
            }
        }
    };

    loadA(0); loadB(0);
    stsAB(0);
    __syncthreads();

    int buf = 0;
    for (int kt = 0; kt < nk; kt++) {
        if (kt + 1 < nk) { loadA(kt + 1); loadB(kt + 1); }

        {
            unsigned ah[4][4], al[4][4], bh[4][2], bl[4][2];
            #pragma unroll
            for (int mf = 0; mf < 4; mf++) {
                int m = wm + mf * 16 + r;
                ah[mf][0] = Ash[buf][c    ][m    ];  al[mf][0] = Asl[buf][c    ][m    ];
                ah[mf][1] = Ash[buf][c    ][m + 8];  al[mf][1] = Asl[buf][c    ][m + 8];
                ah[mf][2] = Ash[buf][c + 4][m    ];  al[mf][2] = Asl[buf][c + 4][m    ];
                ah[mf][3] = Ash[buf][c + 4][m + 8];  al[mf][3] = Asl[buf][c + 4][m + 8];
            }
            #pragma unroll
            for (int nf = 0; nf < 4; nf++) {
                int n = wn + nf * 8 + r;
                bh[nf][0] = Bsh[buf][c    ][n];  bl[nf][0] = Bsl[buf][c    ][n];
                bh[nf][1] = Bsh[buf][c + 4][n];  bl[nf][1] = Bsl[buf][c + 4][n];
            }
            #pragma unroll
            for (int mf = 0; mf < 4; mf++)
                #pragma unroll
                for (int nf = 0; nf < 4; nf++) {
                    MMA_BF16(acc[mf][nf], ah[mf], bh[nf]);
                    MMA_BF16(acc[mf][nf], ah[mf], bl[nf]);
                    MMA_BF16(acc[mf][nf], al[mf], bh[nf]);
                }
        }

        if (kt + 1 < nk) {
            stsAB(buf ^ 1);
            __syncthreads();
            buf ^= 1;
        }
    }

    #pragma unroll
    for (int mf = 0; mf < 4; mf++) {
        int gm = m0 + wm + mf * 16 + r;
        #pragma unroll
        for (int nf = 0; nf < 4; nf++) {
            int gn = n0 + wn + nf * 8 + c * 2;
            float b0 = 0.f, b1 = 0.f;
            if (EPI == 1) { b0 = bias[gn]; b1 = bias[gn + 1]; }
            #pragma unroll
            for (int half = 0; half < 2; half++) {
                int row = gm + half * 8;
                float v0 = acc[mf][nf][half * 2 + 0] * alpha_c;
                float v1 = acc[mf][nf][half * 2 + 1] * alpha_c;
                if (EPI == 1) {
                    v0 += b0; v0 = v0 / (1.f + __expf(-v0));
                    v1 += b1; v1 = v1 / (1.f + __expf(-v1));
                }
                if (EPI == 2) {
                    v0 = fmaxf(v0, 0.f); v0 *= v0;
                    v1 = fmaxf(v1, 0.f); v1 *= v1;
                }
                if (OPS == 1) {
                    Cps[(long long)row * (ldc >> 1) + (gn >> 1)] = packpair2(v0, v1);
                } else {
                    float2* cp = (float2*)&Cf[(long long)row * ldc + gn];
                    if (ACC) {
                        float2 old = *cp;
                        old.x += v0; old.y += v1;
                        *cp = old;
                    } else {
                        float2 nv; nv.x = v0; nv.y = v1;
                        *cp = nv;
                    }
                }
            }
        }
    }
}

// ---------------- weight concat pre-split: pswcat[kp][n], bcat ----
__global__ void wcat_k(const float* __restrict__ Wh, const float* __restrict__ Wq,
                       const float* __restrict__ bh, const float* __restrict__ bq,
                       const float* __restrict__ gh, const float* __restrict__ gq,
                       uint2* __restrict__ Wc, float* __restrict__ bc) {
    int idx = blockIdx.x * 256 + threadIdx.x;   // over (D/2)*NCAT
    if (idx >= (D_/2) * NCAT) return;
    int kp = idx / NCAT, n = idx - kp * NCAT;
    float v0, v1;
    if (n < H_) { v0 = Wh[(2*kp)*H_ + n] * gh[0]; v1 = Wh[(2*kp+1)*H_ + n] * gh[0]; }
    else        { int q = n - H_; v0 = Wq[(2*kp)*QK_ + q] * gq[0]; v1 = Wq[(2*kp+1)*QK_ + q] * gq[0]; }
    Wc[idx] = packpair2(v0, v1);
    if (idx < NCAT) bc[idx] = (idx < H_) ? bh[idx] : bq[idx - H_];
}

// ---------------- Wo pre-split: pswo[kp][n] ----
__global__ void wsplit_k(const float* __restrict__ Wo, uint2* __restrict__ Wps) {
    int idx = blockIdx.x * 256 + threadIdx.x;   // over 512*512
    if (idx >= D_ * D_) return;
    int kp = idx / D_, n = idx - kp * D_;
    Wps[idx] = packpair2(Wo[(2*kp)*D_ + n], Wo[(2*kp+1)*D_ + n]);
}

// ---------------- split-K reduce + pre-split lkvu ----------------
__global__ void lkvured_k(const float* __restrict__ part, uint2* __restrict__ out) {
    int i = blockIdx.x * 256 + threadIdx.x;     // over B*(QK/2)*H
    const int per = (QK_/2) * H_;
    int b = i / per;
    int rem = i - b * per;
    int kp = rem / H_, h = rem - kp * H_;
    float s0 = 0.f, s1 = 0.f;
    #pragma unroll
    for (int sp = 0; sp < NSPLIT; sp++) {
        const float* p = part + ((long long)(b * NSPLIT + sp)) * QK_ * H_;
        s0 += p[(2*kp)*H_ + h];
        s1 += p[(2*kp+1)*H_ + h];
    }
    out[i] = packpair2(s0, s1);
}

// ---------------- transpose x (B,D,S) -> hstate (B,S,D) ----------------
__global__ void transpose_in_k(const float* __restrict__ X, float* __restrict__ Hst) {
    __shared__ float t[32][33];
    int b = blockIdx.z;
    int s0 = blockIdx.x * 32, d0 = blockIdx.y * 32;
    for (int i = threadIdx.y; i < 32; i += 8)
        t[i][threadIdx.x] = X[((long long)b*D_ + d0 + i)*S_ + s0 + threadIdx.x];
    __syncthreads();
    for (int i = threadIdx.y; i < 32; i += 8)
        Hst[((long long)b*S_ + s0 + i)*D_ + d0 + threadIdx.x] = t[threadIdx.x][i];
}

// ---------------- token-shift + scalenorm -> pre-split psnx ----------
__global__ void buildnx_k(const float* __restrict__ Hst, uint2* __restrict__ PSNX) {
    __shared__ float red[128];
    long long row = blockIdx.x;
    int s = (int)(row % S_);
    int tid = threadIdx.x;
    float4 xv;
    if (tid < 64) {
        if (s > 0) xv = *(const float4*)&Hst[(row-1)*D_ + tid*4];
        else       xv = make_float4(0.f, 0.f, 0.f, 0.f);
    } else {
        xv = *(const float4*)&Hst[row*D_ + tid*4];
    }
    float ss = xv.x*xv.x + xv.y*xv.y + xv.z*xv.z + xv.w*xv.w;
    ss = blockReduceSum(ss, red, 128);
    float inv = 1.f / fmaxf(sqrtf(ss * (1.f/D_)), 1e-5f);
    PSNX[row*(D_/2) + tid*2    ] = packpair2(xv.x*inv, xv.y*inv);
    PSNX[row*(D_/2) + tid*2 + 1] = packpair2(xv.z*inv, xv.w*inv);
}

// ---------------- depthwise conv (R4 form) + optional pre-split dual write ----
__global__ void __launch_bounds__(256) dwconv_k(
    const float* __restrict__ X, const float* __restrict__ Kw,
    float* __restrict__ Y, float* __restrict__ R, uint2* __restrict__ PSY,
    int C, int ldin, int ADD)
{
    __shared__ float sh[80][32];
    __shared__ float sk[32][KS_];
    int c0 = blockIdx.x*32, s0 = blockIdx.y*64, b = blockIdx.z;
    int tid = threadIdx.x;
    for (int i = tid; i < 80*32; i += 256) {
        int rr = i >> 5, cc = i & 31;
        int s = s0 + rr - 8;
        float v = 0.f;
        if (s >= 0 && s < S_) v = X[((long long)b*S_ + s)*ldin + c0 + cc];
        sh[rr][cc] = v;
    }
    for (int i = tid; i < 32*KS_; i += 256) {
        int cc = i / KS_, t = i - cc*KS_;
        sk[cc][t] = Kw[(c0+cc)*KS_ + t];
    }
    __syncthreads();
    int cc = tid & 31, wid = tid >> 5;
    #pragma unroll
    for (int jj = 0; jj < 4; jj++) {
        int sl0 = wid*8 + 2*jj;
        float a0 = sh[sl0+8][cc];
        #pragma unroll
        for (int t = 0; t < KS_; t++) a0 = fmaf(sh[sl0+t][cc], sk[cc][t], a0);
        int sl1 = sl0 + 1;
        float a1 = sh[sl1+8][cc];
        #pragma unroll
        for (int t = 0; t < KS_; t++) a1 = fmaf(sh[sl1+t][cc], sk[cc][t], a1);
        long long o0 = ((long long)b*S_ + s0 + sl0)*C + c0 + cc;
        long long o1 = o0 + C;
        if (ADD) { R[o0] += a0; R[o1] += a1; }
        else {
            Y[o0] = a0; Y[o1] = a1;
            if (PSY) {
                long long spi = (long long)b*(S_/2) + ((s0 + sl0) >> 1);
                PSY[spi*C + c0 + cc] = packpair2(a0, a1);
            }
        }
    }
}

// ---------------- heads + rotary -> pre-split qq/lq/kq + fp32 lk ----------
__global__ void rotary_k(const float* __restrict__ QKin, const float* __restrict__ Gm,
                         const float* __restrict__ Bt,
                         uint2* __restrict__ PQQ, uint2* __restrict__ PLQ,
                         uint2* __restrict__ PKQ, float* __restrict__ OLK) {
    long long row = blockIdx.x;
    int s = (int)(row % S_);
    int d = threadIdx.x;  // 128
    float base = QKin[row*QK_ + d];
    float cc = 1.f, sn = 0.f;
    bool rot = (d < 32);
    if (rot) {
        float invf = powf(10000.f, -(float)(2*(d >> 1)) / 32.f);
        float ang = (float)s * invf;
        sincosf(ang, &sn, &cc);
    }
    float sgn = (d & 1) ? 1.f : -1.f;
    uint2* pouts[3] = {PQQ, PLQ, PKQ};
    #pragma unroll
    for (int h = 0; h < 4; h++) {
        float t = base*Gm[h*QK_ + d] + Bt[h*QK_ + d];
        float o = t;
        if (rot) {
            float p = __shfl_xor_sync(0xffffffffu, t, 1);
            o = t*cc + sgn*p*sn;
        }
        if (h == 3) {
            OLK[row*QK_ + d] = o;
        } else {
            float other = __shfl_xor_sync(0xffffffffu, o, 1);
            if ((d & 1) == 0)
                pouts[h][row*(QK_/2) + (d >> 1)] = packpair2(o, other);
        }
    }
}

// ---------------- gating + scalenorm -> pre-split psgate ------------
__global__ void gating_k(const float* __restrict__ QVU, const float* __restrict__ H2b,
                         const float* __restrict__ gop, uint2* __restrict__ PSOUT) {
    __shared__ float red[256];
    long long row = blockIdx.x;
    int tid = threadIdx.x;
    float o[4]; float ss = 0.f;
    #pragma unroll
    for (int j = 0; j < 4; j++) {
        int e = tid*4 + j;
        float av = QVU[row*2048 + e];
        float au = QVU[row*2048 + 1024 + e];
        float vv = H2b[row*2048 + e];
        float uu = H2b[row*2048 + 1024 + e];
        float sg = 1.f/(1.f + __expf(-av*uu));
        float val = au * vv * sg;
        o[j] = val; ss += val*val;
    }
    ss = blockReduceSum(ss, red, 256);
    float sc = gop[0] / fmaxf(sqrtf(ss * (1.f/1024.f)), 1e-5f);
    PSOUT[row*512 + tid*2    ] = packpair2(o[0]*sc, o[1]*sc);
    PSOUT[row*512 + tid*2 + 1] = packpair2(o[2]*sc, o[3]*sc);
}

// ---------------- final LN + groupnorm partials ------------
__global__ void ln_k(const float* __restrict__ Hst, const float* __restrict__ lng,
                     const float* __restrict__ lnb, float* __restrict__ Y,
                     float* __restrict__ PS, float* __restrict__ PS2) {
    __shared__ float red[128];
    long long row = blockIdx.x;
    int tid = threadIdx.x;
    float v[4]; float s = 0.f, s2 = 0.f;
    #pragma unroll
    for (int j = 0; j < 4; j++) {
        float t = Hst[row*D_ + tid + j*128];
        v[j] = t; s += t; s2 += t*t;
    }
    s  = blockReduceSum(s,  red, 128);
    s2 = blockReduceSum(s2, red, 128);
    float mu = s * (1.f/D_);
    float var = s2 * (1.f/D_) - mu*mu;
    float rstd = rsqrtf(var + 1e-6f);
    float ys = 0.f, ys2 = 0.f;
    #pragma unroll
    for (int j = 0; j < 4; j++) {
        int d = tid + j*128;
        float y = (v[j]-mu)*rstd*lng[d] + lnb[d];
        Y[row*D_ + d] = y;
        ys += y; ys2 += y*y;
    }
    ys  = blockReduceSum(ys,  red, 128);
    ys2 = blockReduceSum(ys2, red, 128);
    if (tid == 0) { PS[row] = ys; PS2[row] = ys2; }
}

__global__ void gnred_k(const float* __restrict__ PS, const float* __restrict__ PS2,
                        float* __restrict__ stats) {
    __shared__ double rd[256], rd2[256];
    int b = blockIdx.x, tid = threadIdx.x;
    double s = 0, s2 = 0;
    for (int i = tid; i < S_; i += 256) { s += PS[b*S_+i]; s2 += PS2[b*S_+i]; }
    rd[tid] = s; rd2[tid] = s2; __syncthreads();
    for (int o = 128; o > 0; o >>= 1) {
        if (tid < o) { rd[tid] += rd[tid+o]; rd2[tid] += rd2[tid+o]; }
        __syncthreads();
    }
    if (tid == 0) {
        double n = (double)D_ * (double)S_;
        double m = rd[0] / n;
        double var = rd2[0] / n - m*m;
        stats[b*2]     = (float)m;
        stats[b*2 + 1] = (float)(1.0/sqrt(var + 1e-8));
    }
}

__global__ void gnapply_k(const float* __restrict__ Y, const float* __restrict__ stats,
                          const float* __restrict__ gw, const float* __restrict__ gb,
                          const float* __restrict__ X, float* __restrict__ O) {
    __shared__ float t[32][33];
    int b = blockIdx.z;
    int s0 = blockIdx.x*32, d0 = blockIdx.y*32;
    for (int i = threadIdx.y; i < 32; i += 8)
        t[i][threadIdx.x] = Y[((long long)b*S_ + s0 + i)*D_ + d0 + threadIdx.x];
    __syncthreads();
    float m = stats[b*2], rstd = stats[b*2 + 1];
    for (int i = threadIdx.y; i < 32; i += 8) {
        int d = d0 + i, s = s0 + threadIdx.x;
        long long oi = ((long long)b*D_ + d)*S_ + s;
        O[oi] = (t[threadIdx.x][i] - m)*rstd*gw[d] + gb[d] + X[oi];
    }
}

// ---------------- host orchestration ----------------
extern "C" void kernel_launch(void* const* d_in, const int* in_sizes, int n_in,
                              void* d_out, int out_size)
{
    const float* x      = (const float*)d_in[0];
    const float* g_hid  = (const float*)d_in[1];
    const float* W_hid  = (const float*)d_in[2];
    const float* b_hid  = (const float*)d_in[3];
    const float* k_hid  = (const float*)d_in[4];
    const float* g_qkp  = (const float*)d_in[5];
    const float* W_qkp  = (const float*)d_in[6];
    const float* b_qkp  = (const float*)d_in[7];
    const float* k_qkp  = (const float*)d_in[8];
    const float* g_outp = (const float*)d_in[9];
    const float* W_outp = (const float*)d_in[10];
    const float* b_outp = (const float*)d_in[11];
    const float* k_outp = (const float*)d_in[12];
    const float* gamma  = (const float*)d_in[13];
    const float* beta   = (const float*)d_in[14];
    const float* ln_g   = (const float*)d_in[15];
    const float* ln_b   = (const float*)d_in[16];
    const float* gn_w   = (const float*)d_in[17];
    const float* gn_b   = (const float*)d_in[18];
    float* out = (float*)d_out;

    float *hstate,*yln,*hq,*h1,*h2,*qk2,*blk,*o1,*lkvup,*bcat,*ps,*ps2,*stats;
    uint2 *psnx,*pswcat,*psbqq,*psblq,*psbkq,*psattn,*psh2,*psgate,*pswo,*pslkvu;
    cudaGetSymbolAddress((void**)&hstate, g_hstate);
    cudaGetSymbolAddress((void**)&yln,    g_yln);
    cudaGetSymbolAddress((void**)&hq,     g_hq);
    cudaGetSymbolAddress((void**)&h1,     g_h1);
    cudaGetSymbolAddress((void**)&h2,     g_h2);
    cudaGetSymbolAddress((void**)&qk2,    g_qk2);
    cudaGetSymbolAddress((void**)&blk,    g_blk);
    cudaGetSymbolAddress((void**)&o1,     g_o1);
    cudaGetSymbolAddress((void**)&lkvup,  g_lkvup);
    cudaGetSymbolAddress((void**)&bcat,   g_bcat);
    cudaGetSymbolAddress((void**)&ps,     g_ps);
    cudaGetSymbolAddress((void**)&ps2,    g_ps2);
    cudaGetSymbolAddress((void**)&stats,  g_stats);
    cudaGetSymbolAddress((void**)&psnx,   g_psnx);
    cudaGetSymbolAddress((void**)&pswcat, g_pswcat);
    cudaGetSymbolAddress((void**)&psbqq,  g_psbqq);
    cudaGetSymbolAddress((void**)&psblq,  g_psblq);
    cudaGetSymbolAddress((void**)&psbkq,  g_psbkq);
    cudaGetSymbolAddress((void**)&psattn, g_psattn);
    cudaGetSymbolAddress((void**)&psh2,   g_psh2);
    cudaGetSymbolAddress((void**)&psgate, g_psgate);
    cudaGetSymbolAddress((void**)&pswo,   g_pswo);
    cudaGetSymbolAddress((void**)&pslkvu, g_pslkvu);

    transpose_in_k<<<dim3(S_/32, D_/32, B_), dim3(32, 8)>>>(x, hstate);

    for (int l = 0; l < 2; l++) {
        const float* Wh = W_hid  + (size_t)l*D_*H_;
        const float* bh = b_hid  + l*H_;
        const float* kh = k_hid  + (size_t)l*H_*KS_;
        const float* Wq = W_qkp  + (size_t)l*D_*QK_;
        const float* bq = b_qkp  + l*QK_;
        const float* kq = k_qkp  + (size_t)l*QK_*KS_;
        const float* Wo = W_outp + (size_t)l*2*D_*D_;
        const float* bo = b_outp + l*D_;
        const float* ko = k_outp + (size_t)l*D_*KS_;
        const float* gm = gamma  + l*4*QK_;
        const float* bt = beta   + l*4*QK_;

        wcat_k<<<((D_/2)*NCAT + 255)/256, 256>>>(Wh, Wq, bh, bq, g_hid + l, g_qkp + l, pswcat, bcat);
        wsplit_k<<<(D_*D_ + 255)/256, 256>>>(Wo, pswo);

        buildnx_k<<<BS_, 128>>>(hstate, psnx);

        // hq = silu(psnx @ pswcat + bcat)    [16384,2176,512]
        tgemm_k<1,2,2,false,0><<<dim3(NCAT/TBN, BS_/TBM, 1), 256>>>(
            psnx, pswcat, hq, bcat, 1.f,
            BS_, NCAT, D_, D_/2, NCAT, NCAT, 0, 0, 0, 1);

        // h2 = h1 + dwconv(h1); dual write psh2
        dwconv_k<<<dim3(H_/32, S_/64, B_), 256>>>(hq, kh, h2, nullptr, psh2, H_, NCAT, 0);
        dwconv_k<<<dim3(QK_/32, S_/64, B_), 256>>>(hq + H_, kq, qk2, nullptr, nullptr, QK_, NCAT, 0);
        rotary_k<<<BS_, 128>>>(qk2, gm, bt, psbqq, psblq, psbkq, blk);

        // attn = relu(qq@kq^T/256)^2 -> pre-split out   64 x [256,256,128]
        tgemm_k<2,2,3,false,1><<<dim3(GSZ_/TBN, GSZ_/TBM, B_*NGRP), 256>>>(
            psbqq, psbkq, psattn, nullptr, 1.f/(float)GSZ_,
            GSZ_, GSZ_, QK_, QK_/2, QK_/2, GSZ_,
            (long long)GSZ_*(QK_/2), (long long)GSZ_*(QK_/2), (long long)GSZ_*(GSZ_/2), 1);

        // qvu = psattn @ psh2(group)          64 x [256,2048,256]
        tgemm_k<0,2,2,false,0><<<dim3(H_/TBN, GSZ_/TBM, B_*NGRP), 256>>>(
            psattn, psh2, h1, nullptr, 1.f,
            GSZ_, H_, GSZ_, GSZ_/2, H_, H_,
            (long long)GSZ_*(GSZ_/2), (long long)(GSZ_/2)*H_, (long long)GSZ_*H_, 1);

        // lkvu partials = blk^T @ psh2 / S    split-K=8
        tgemm_k<0,1,2,false,0><<<dim3(H_/TBN, QK_/TBM, B_*NSPLIT), 256>>>(
            blk, psh2, lkvup, nullptr, 1.f/(float)S_,
            QK_, H_, S_/NSPLIT, QK_, H_, H_,
            (long long)S_*QK_, (long long)(S_/2)*H_, (long long)QK_*H_, NSPLIT);
        lkvured_k<<<(B_*(QK_/2)*H_)/256, 256>>>(lkvup, pslkvu);

        // qvu += psblq @ pslkvu               2 x [8192,2048,128]
        tgemm_k<0,2,2,true,0><<<dim3(H_/TBN, S_/TBM, B_), 256>>>(
            psblq, pslkvu, h1, nullptr, 1.f,
            S_, H_, QK_, QK_/2, H_, H_,
            (long long)S_*(QK_/2), (long long)(QK_/2)*H_, (long long)S_*H_, 1);

        gating_k<<<BS_, 256>>>(h1, h2, g_outp + l, psgate);

        // o1 = silu(psgate @ pswo + bo)       [16384,512,1024]
        tgemm_k<1,2,2,false,0><<<dim3(D_/TBN, BS_/TBM, 1), 256>>>(
            psgate, pswo, o1, bo, 1.f,
            BS_, D_, 2*D_, D_, D_, D_, 0, 0, 0, 1);

        dwconv_k<<<dim3(D_/32, S_/64, B_), 256>>>(o1, ko, nullptr, hstate, nullptr, D_, D_, 1);
    }

    ln_k<<<BS_, 128>>>(hstate, ln_g, ln_b, yln, ps, ps2);
    gnred_k<<<B_, 256>>>(ps, ps2, stats);
    gnapply_k<<<dim3(S_/32, D_/32, B_), dim3(32, 8)>>>(yln, stats, gn_w, gn_b, x, out);
}